// round 12
// baseline (speedup 1.0000x reference)
#include <cuda_runtime.h>
#include <cstdint>

#define NPTS    6890
#define BF      20670           // floats per batch per tensor
#define B_MAX   1024
#define SPLIT   4               // CTAs per batch
#define THREADS 256
#define NWARPS  8
#define PBASE   5184            // portion stride (mult of 48)
#define F_LOAD  20672           // padded stream length
#define NU      3445            // 2-point units per batch
#define SLOT    5184            // smem slot floats (max portion size)

// smem layout (float offsets); 42104 B/CTA -> 5 CTAs/SM
#define SM_PRED 0
#define SM_GT   5184
#define SM_RED  10368           // NWARPS*16 = 128
#define SM_STAT 10496           // 16
#define SM_PRM  10512           // 12
#define SM_MBAR 10524           // byte 42096, 8B aligned
#define SMEM_FLOATS (SM_MBAR + 2)
#define SMEM_BYTES  (SMEM_FLOATS * 4)

// cross-CTA sync state (static device globals; reset kernel zeroes cnt/flag)
__device__ float    g_part[B_MAX * SPLIT * 16];
__device__ float    g_prmG[B_MAX * 12];
__device__ unsigned g_cnt[B_MAX];
__device__ unsigned g_flag[B_MAX];

__device__ __forceinline__ uint32_t smem_addr(const void* p) {
    return (uint32_t)__cvta_generic_to_shared(p);
}

__device__ __forceinline__ void mbar_wait0(uint32_t mbarA) {
    uint32_t done = 0;
    while (!done) {
        asm volatile("{\n\t.reg .pred p;\n\t"
                     "mbarrier.try_wait.parity.acquire.cta.shared::cta.b64 p, [%1], 0, 0x989680;\n\t"
                     "selp.b32 %0, 1, 0, p;\n\t}"
                     : "=r"(done) : "r"(mbarA) : "memory");
    }
}

__device__ __forceinline__ void accum_pt(float* a,
                                         float p0, float p1, float p2,
                                         float g0, float g1, float g2) {
    a[0] += p0; a[1] += p1; a[2] += p2;
    a[3] += g0; a[4] += g1; a[5] += g2;
    a[6] = fmaf(p0, p0, fmaf(p1, p1, fmaf(p2, p2, a[6])));
    a[7]  = fmaf(p0, g0, a[7]);
    a[8]  = fmaf(p0, g1, a[8]);
    a[9]  = fmaf(p0, g2, a[9]);
    a[10] = fmaf(p1, g0, a[10]);
    a[11] = fmaf(p1, g1, a[11]);
    a[12] = fmaf(p1, g2, a[12]);
    a[13] = fmaf(p2, g0, a[13]);
    a[14] = fmaf(p2, g1, a[14]);
    a[15] = fmaf(p2, g2, a[15]);
}

__global__ void reset_sync_kernel() {
    int t = blockIdx.x * blockDim.x + threadIdx.x;
    if (t < B_MAX) { g_cnt[t] = 0; g_flag[t] = 0; }
}

__global__ void __launch_bounds__(THREADS, 5)
procrustes_l1_kernel(const float* __restrict__ pred,
                     const float* __restrict__ gt,
                     float* __restrict__ out) {
    extern __shared__ float sm[];
    float* predS = sm + SM_PRED;
    float* gtS   = sm + SM_GT;
    float* redS  = sm + SM_RED;
    float* statS = sm + SM_STAT;
    float* prm   = sm + SM_PRM;

    const int tid = threadIdx.x;
    const int b = (int)(blockIdx.x >> 2);
    const int pi = (int)(blockIdx.x & 3);
    const size_t gstart = (size_t)b * BF;
    const int pad = (int)(gstart & 3);            // 0 (even b) or 2 (odd b)

    // portion boundaries in padded-stream coords: ≡ pad (mod 6), ≡ 0 (mod 4)
    const int adj = pad ? 4 : 0;
    const int e0 = (pi == 0) ? 0 : pi * PBASE - adj;
    const int e1 = (pi == 3) ? F_LOAD : (pi + 1) * PBASE - adj;
    const uint32_t bytes = (uint32_t)(e1 - e0) * 4u;

    const uint32_t mbarA = smem_addr(sm + SM_MBAR);

    uint64_t polFirst;
    asm volatile("createpolicy.fractional.L2::evict_first.b64 %0, 1.0;" : "=l"(polFirst));

    if (tid == 0) {
        asm volatile("mbarrier.init.shared.b64 [%0], 1;" :: "r"(mbarA) : "memory");
    }
    __syncthreads();

    // --- one-shot TMA load of this portion (pred + gt) ---
    if (tid == 0) {
        const float* srcP = pred + (gstart - (size_t)pad) + e0;
        const float* srcG = gt   + (gstart - (size_t)pad) + e0;
        asm volatile("mbarrier.arrive.expect_tx.shared.b64 _, [%0], %1;"
                     :: "r"(mbarA), "r"(2u * bytes) : "memory");
        asm volatile("cp.async.bulk.shared::cluster.global.mbarrier::complete_tx::bytes.L2::cache_hint"
                     " [%0], [%1], %2, [%3], %4;"
                     :: "r"(smem_addr(predS)), "l"(srcP), "r"(bytes), "r"(mbarA), "l"(polFirst) : "memory");
        asm volatile("cp.async.bulk.shared::cluster.global.mbarrier::complete_tx::bytes.L2::cache_hint"
                     " [%0], [%1], %2, [%3], %4;"
                     :: "r"(smem_addr(gtS)), "l"(srcG), "r"(bytes), "r"(mbarA), "l"(polFirst) : "memory");
    }
    mbar_wait0(mbarA);

    // --- reduce 16 stats over this portion's units ---
    const int uS = (e0 - pad + 5) / 6;
    int uE = (e1 - pad) / 6; if (uE > NU) uE = NU;
    const float* pc = predS - e0;   // index by stream coord l
    const float* gc = gtS - e0;

    float acc[16];
#pragma unroll
    for (int i = 0; i < 16; i++) acc[i] = 0.f;

    for (int u = uS + tid; u < uE; u += THREADS) {
        int l = pad + 6 * u;
        float2 pa = *(const float2*)(pc + l);
        float2 pb = *(const float2*)(pc + l + 2);
        float2 pcc = *(const float2*)(pc + l + 4);
        float2 ga = *(const float2*)(gc + l);
        float2 gb = *(const float2*)(gc + l + 2);
        float2 gcc = *(const float2*)(gc + l + 4);
        accum_pt(acc, pa.x, pa.y, pb.x, ga.x, ga.y, gb.x);
        accum_pt(acc, pb.y, pcc.x, pcc.y, gb.y, gcc.x, gcc.y);
    }

#pragma unroll
    for (int i = 0; i < 16; i++) {
        float v = acc[i];
        v += __shfl_down_sync(0xffffffffu, v, 16);
        v += __shfl_down_sync(0xffffffffu, v, 8);
        v += __shfl_down_sync(0xffffffffu, v, 4);
        v += __shfl_down_sync(0xffffffffu, v, 2);
        v += __shfl_down_sync(0xffffffffu, v, 1);
        acc[i] = v;
    }
    const int lane = tid & 31;
    const int wp = tid >> 5;
    if (lane == 0) {
#pragma unroll
        for (int i = 0; i < 16; i++) redS[wp * 16 + i] = acc[i];
    }
    __syncthreads();
    if (tid < 16) {
        float s = redS[tid];
#pragma unroll
        for (int w = 1; w < NWARPS; w++) s += redS[w * 16 + tid];
        statS[tid] = s;
        g_part[((size_t)b * SPLIT + pi) * 16 + tid] = s;   // publish partial
    }
    __syncthreads();

    // --- cross-CTA stat combine: last arriver solves; others poll flag ---
    if (tid == 0) {
        __threadfence();
        unsigned old = atomicAdd(&g_cnt[b], 1u);
        if (old == SPLIT - 1) {
            // ---- solver path ----
            __threadfence();
            float st[16];
#pragma unroll
            for (int k = 0; k < 16; k++) st[k] = 0.f;
            for (int j = 0; j < SPLIT; j++) {         // fixed order -> deterministic
                volatile const float* vp = g_part + ((size_t)b * SPLIT + j) * 16;
#pragma unroll
                for (int k = 0; k < 16; k++) st[k] += vp[k];
            }

            const float fN = (float)NPTS;
            const float invN = 1.0f / fN;
            float mu1[3], mu2[3];
#pragma unroll
            for (int i = 0; i < 3; i++) { mu1[i] = st[i] * invN; mu2[i] = st[3 + i] * invN; }

            float K[3][3];
#pragma unroll
            for (int i = 0; i < 3; i++)
#pragma unroll
                for (int j = 0; j < 3; j++)
                    K[i][j] = st[7 + 3 * i + j] - fN * mu1[i] * mu2[j] + 1e-8f;

            float var1 = st[6] - fN * (mu1[0]*mu1[0] + mu1[1]*mu1[1] + mu1[2]*mu1[2]);

            float A[3][3];
#pragma unroll
            for (int i = 0; i < 3; i++)
#pragma unroll
                for (int j = 0; j < 3; j++)
                    A[i][j] = K[0][i]*K[0][j] + K[1][i]*K[1][j] + K[2][i]*K[2][j];

            float V[3][3] = { {1.f,0.f,0.f}, {0.f,1.f,0.f}, {0.f,0.f,1.f} };

            for (int sweep = 0; sweep < 6; sweep++) {
#pragma unroll
                for (int pair = 0; pair < 3; pair++) {
                    int p = (pair == 2) ? 1 : 0;
                    int q = (pair == 0) ? 1 : 2;
                    float apq = A[p][q];
                    if (fabsf(apq) > 1e-18f) {
                        float tau = (A[q][q] - A[p][p]) / (2.f * apq);
                        float tt = copysignf(1.f, tau) / (fabsf(tau) + sqrtf(fmaf(tau, tau, 1.f)));
                        float c = rsqrtf(fmaf(tt, tt, 1.f));
                        float s = tt * c;
#pragma unroll
                        for (int k = 0; k < 3; k++) {
                            float akp = A[k][p], akq = A[k][q];
                            A[k][p] = c*akp - s*akq;
                            A[k][q] = s*akp + c*akq;
                        }
#pragma unroll
                        for (int k = 0; k < 3; k++) {
                            float apk = A[p][k], aqk = A[q][k];
                            A[p][k] = c*apk - s*aqk;
                            A[q][k] = s*apk + c*aqk;
                        }
#pragma unroll
                        for (int k = 0; k < 3; k++) {
                            float vkp = V[k][p], vkq = V[k][q];
                            V[k][p] = c*vkp - s*vkq;
                            V[k][q] = s*vkp + c*vkq;
                        }
                    }
                }
            }

            float dd[3] = { A[0][0], A[1][1], A[2][2] };
            int oo[3] = { 0, 1, 2 };
            if (dd[oo[0]] < dd[oo[1]]) { int t = oo[0]; oo[0] = oo[1]; oo[1] = t; }
            if (dd[oo[0]] < dd[oo[2]]) { int t = oo[0]; oo[0] = oo[2]; oo[2] = t; }
            if (dd[oo[1]] < dd[oo[2]]) { int t = oo[1]; oo[1] = oo[2]; oo[2] = t; }

            float v0[3], v1[3], v2[3];
#pragma unroll
            for (int i = 0; i < 3; i++) { v0[i] = V[i][oo[0]]; v1[i] = V[i][oo[1]]; v2[i] = V[i][oo[2]]; }
            float det =
                v0[0]*(v1[1]*v2[2] - v1[2]*v2[1]) -
                v0[1]*(v1[0]*v2[2] - v1[2]*v2[0]) +
                v0[2]*(v1[0]*v2[1] - v1[1]*v2[0]);
            if (det < 0.f) { v2[0] = -v2[0]; v2[1] = -v2[1]; v2[2] = -v2[2]; }

            float Kv0[3], Kv1[3];
#pragma unroll
            for (int i = 0; i < 3; i++) {
                Kv0[i] = K[i][0]*v0[0] + K[i][1]*v0[1] + K[i][2]*v0[2];
                Kv1[i] = K[i][0]*v1[0] + K[i][1]*v1[1] + K[i][2]*v1[2];
            }
            float r0 = rsqrtf(Kv0[0]*Kv0[0] + Kv0[1]*Kv0[1] + Kv0[2]*Kv0[2] + 1e-30f);
            float u0[3] = { Kv0[0]*r0, Kv0[1]*r0, Kv0[2]*r0 };
            float d01 = u0[0]*Kv1[0] + u0[1]*Kv1[1] + u0[2]*Kv1[2];
            float u1r[3] = { Kv1[0]-d01*u0[0], Kv1[1]-d01*u0[1], Kv1[2]-d01*u0[2] };
            float r1 = rsqrtf(u1r[0]*u1r[0] + u1r[1]*u1r[1] + u1r[2]*u1r[2] + 1e-30f);
            float u1[3] = { u1r[0]*r1, u1r[1]*r1, u1r[2]*r1 };
            float w[3] = { u0[1]*u1[2] - u0[2]*u1[1],
                           u0[2]*u1[0] - u0[0]*u1[2],
                           u0[0]*u1[1] - u0[1]*u1[0] };

            float R[3][3];
#pragma unroll
            for (int i = 0; i < 3; i++)
#pragma unroll
                for (int j = 0; j < 3; j++)
                    R[i][j] = v0[i]*u0[j] + v1[i]*u1[j] + v2[i]*w[j];

            float tr = 0.f;
#pragma unroll
            for (int i = 0; i < 3; i++)
#pragma unroll
                for (int j = 0; j < 3; j++)
                    tr += R[i][j] * K[j][i];
            float scale = tr / var1;

#pragma unroll
            for (int i = 0; i < 3; i++)
#pragma unroll
                for (int j = 0; j < 3; j++)
                    R[i][j] *= scale;

            float prmv[12];
#pragma unroll
            for (int i = 0; i < 3; i++)
#pragma unroll
                for (int j = 0; j < 3; j++)
                    prmv[3 * i + j] = R[i][j];
#pragma unroll
            for (int i = 0; i < 3; i++)
                prmv[9 + i] = mu2[i] - (R[i][0]*mu1[0] + R[i][1]*mu1[1] + R[i][2]*mu1[2]);

#pragma unroll
            for (int k = 0; k < 12; k++) {
                g_prmG[b * 12 + k] = prmv[k];
                prm[k] = prmv[k];
            }
            __threadfence();
            asm volatile("st.release.gpu.global.u32 [%0], %1;"
                         :: "l"(&g_flag[b]), "r"(1u) : "memory");
        } else {
            // ---- poller path ----
            uint32_t f = 0;
            do {
                asm volatile("ld.acquire.gpu.global.u32 %0, [%1];"
                             : "=r"(f) : "l"(&g_flag[b]) : "memory");
                if (!f) __nanosleep(200);
            } while (!f);
            volatile const float* vp = g_prmG + b * 12;
#pragma unroll
            for (int k = 0; k < 12; k++) prm[k] = vp[k];
        }
    }
    __syncthreads();

    // --- apply: out = |R*p + t - g| in place in predS ---
    float Rs[9], tv[3];
#pragma unroll
    for (int i = 0; i < 9; i++) Rs[i] = prm[i];
    tv[0] = prm[9]; tv[1] = prm[10]; tv[2] = prm[11];

    float* pw = predS - e0;
    for (int u = uS + tid; u < uE; u += THREADS) {
        int l = pad + 6 * u;
        float2 pa = *(const float2*)(pw + l);
        float2 pb = *(const float2*)(pw + l + 2);
        float2 pcc = *(const float2*)(pw + l + 4);
        float2 ga = *(const float2*)(gc + l);
        float2 gb = *(const float2*)(gc + l + 2);
        float2 gcc = *(const float2*)(gc + l + 4);

        float p0x = pa.x, p0y = pa.y, p0z = pb.x;
        float p1x = pb.y, p1y = pcc.x, p1z = pcc.y;

        float o0x = fabsf(fmaf(Rs[0], p0x, fmaf(Rs[1], p0y, fmaf(Rs[2], p0z, tv[0]))) - ga.x);
        float o0y = fabsf(fmaf(Rs[3], p0x, fmaf(Rs[4], p0y, fmaf(Rs[5], p0z, tv[1]))) - ga.y);
        float o0z = fabsf(fmaf(Rs[6], p0x, fmaf(Rs[7], p0y, fmaf(Rs[8], p0z, tv[2]))) - gb.x);
        float o1x = fabsf(fmaf(Rs[0], p1x, fmaf(Rs[1], p1y, fmaf(Rs[2], p1z, tv[0]))) - gb.y);
        float o1y = fabsf(fmaf(Rs[3], p1x, fmaf(Rs[4], p1y, fmaf(Rs[5], p1z, tv[1]))) - gcc.x);
        float o1z = fabsf(fmaf(Rs[6], p1x, fmaf(Rs[7], p1y, fmaf(Rs[8], p1z, tv[2]))) - gcc.y);

        *(float2*)(pw + l)     = make_float2(o0x, o0y);
        *(float2*)(pw + l + 2) = make_float2(o0z, o1x);
        *(float2*)(pw + l + 4) = make_float2(o1y, o1z);
    }
    __syncthreads();

    // --- store: aligned TMA bulk + edge scalars ---
    if (tid == 0) {
        const int tailAligned = (pad + BF) & ~3;
        int sl0 = (pi == 0 && pad) ? 4 : e0;
        int sl1 = (e1 < tailAligned) ? e1 : tailAligned;
        uint32_t sb = (uint32_t)(sl1 - sl0) * 4u;
        asm volatile("fence.proxy.async.shared::cta;" ::: "memory");
        asm volatile("cp.async.bulk.global.shared::cta.bulk_group.L2::cache_hint [%0], [%1], %2, %3;"
                     :: "l"(out + gstart - (size_t)pad + sl0),
                        "r"(smem_addr(predS + (sl0 - e0))), "r"(sb), "l"(polFirst) : "memory");
        asm volatile("cp.async.bulk.commit_group;" ::: "memory");
        if (pi == 0 && pad) {                    // elements 0,1 at stream l=2,3
            out[gstart]     = predS[2];
            out[gstart + 1] = predS[3];
        }
        if (pi == 3 && !pad) {                   // tail elements 20668,20669
            out[gstart + BF - 2] = predS[(BF - 2) - e0];
            out[gstart + BF - 1] = predS[(BF - 1) - e0];
        }
        asm volatile("cp.async.bulk.wait_group 0;" ::: "memory");
    }
}

extern "C" void kernel_launch(void* const* d_in, const int* in_sizes, int n_in,
                              void* d_out, int out_size) {
    const float* pred = (const float*)d_in[0];
    const float* gt   = (const float*)d_in[1];
    float* out = (float*)d_out;
    int B = in_sizes[0] / BF;   // 1024

    reset_sync_kernel<<<(B_MAX + 255) / 256, 256>>>();

    cudaFuncSetAttribute(procrustes_l1_kernel,
                         cudaFuncAttributeMaxDynamicSharedMemorySize, SMEM_BYTES);
    procrustes_l1_kernel<<<B * SPLIT, THREADS, SMEM_BYTES>>>(pred, gt, out);
}

// round 14
// speedup vs baseline: 1.3408x; 1.3408x over previous
#include <cuda_runtime.h>
#include <cstdint>

#define NPTS    6890
#define BF      20670           // floats per batch per tensor
#define THREADS 320             // 8 consumer warps + 1 loader warp + 1 storer warp
#define CWARPS  8
#define CTHREADS 256
#define CHUNK   1536            // ring-slot floats (6144 B; mult of 48)
#define NB      3               // ring depth (pred/gt and out)
#define F_LOAD  20672           // padded stream length (pad 0 or 2)
#define NC      14              // chunks per pass
#define NU      3445            // 2-point units per batch

// smem layout (float offsets); 56016 B/CTA -> 4 CTAs/SM
#define SM_PRED 0               // 3*1536 = 4608
#define SM_GT   4608
#define SM_OUT  9216
#define SM_RED  13824           // CWARPS*16 = 128
#define SM_STAT 13952           // 16
#define SM_PRM  13968           // 12
#define SM_MBAR 13980           // byte 55920, 8B aligned; 12 mbarriers (96 B)
#define SMEM_FLOATS (SM_MBAR + 24)
#define SMEM_BYTES  (SMEM_FLOATS * 4)

__device__ __forceinline__ uint32_t smem_addr(const void* p) {
    return (uint32_t)__cvta_generic_to_shared(p);
}

__device__ __forceinline__ void mbar_wait(uint32_t mbarA, uint32_t parity) {
    uint32_t done = 0;
    while (!done) {
        asm volatile("{\n\t.reg .pred p;\n\t"
                     "mbarrier.try_wait.parity.acquire.cta.shared::cta.b64 p, [%1], %2, 0x989680;\n\t"
                     "selp.b32 %0, 1, 0, p;\n\t}"
                     : "=r"(done) : "r"(mbarA), "r"(parity) : "memory");
    }
}

__device__ __forceinline__ void mbar_arrive(uint32_t mbarA) {
    asm volatile("mbarrier.arrive.shared.b64 _, [%0];" :: "r"(mbarA) : "memory");
}

// chunk boundary in padded-stream float coords
__device__ __forceinline__ int Eof(int c, int EF) {
    if (c <= 0) return 0;
    int e = EF + (c - 1) * CHUNK;
    return e < F_LOAD ? e : F_LOAD;
}

__device__ __forceinline__ void accum_pt(float* a,
                                         float p0, float p1, float p2,
                                         float g0, float g1, float g2) {
    a[0] += p0; a[1] += p1; a[2] += p2;
    a[3] += g0; a[4] += g1; a[5] += g2;
    a[6] = fmaf(p0, p0, fmaf(p1, p1, fmaf(p2, p2, a[6])));
    a[7]  = fmaf(p0, g0, a[7]);
    a[8]  = fmaf(p0, g1, a[8]);
    a[9]  = fmaf(p0, g2, a[9]);
    a[10] = fmaf(p1, g0, a[10]);
    a[11] = fmaf(p1, g1, a[11]);
    a[12] = fmaf(p1, g2, a[12]);
    a[13] = fmaf(p2, g0, a[13]);
    a[14] = fmaf(p2, g1, a[14]);
    a[15] = fmaf(p2, g2, a[15]);
}

__global__ void __launch_bounds__(THREADS, 4)
procrustes_l1_kernel(const float* __restrict__ pred,
                     const float* __restrict__ gt,
                     float* __restrict__ out) {
    extern __shared__ float sm[];
    float* predR = sm + SM_PRED;
    float* gtR   = sm + SM_GT;
    float* outR  = sm + SM_OUT;
    float* redS  = sm + SM_RED;
    float* statS = sm + SM_STAT;
    float* prm   = sm + SM_PRM;

    const int tid  = threadIdx.x;
    const int wid  = tid >> 5;
    const int lane = tid & 31;
    const int b = (int)blockIdx.x;
    const size_t gstart = (size_t)b * BF;
    const int pad = (int)(gstart & 3);          // 0 (even b) or 2 (odd b)
    const int EF  = pad ? (CHUNK - 4) : CHUNK;  // boundaries ≡ pad (mod 6), ≡ 0 (mod 4)

    const uint32_t mbar0 = smem_addr(sm + SM_MBAR);
#define MB_FULL(s)  (mbar0 + 8u * (uint32_t)(s))
#define MB_CONS(s)  (mbar0 + 24u + 8u * (uint32_t)(s))
#define MB_OFULL(s) (mbar0 + 48u + 8u * (uint32_t)(s))
#define MB_OFREE(s) (mbar0 + 72u + 8u * (uint32_t)(s))

    uint64_t polLast, polFirst;
    asm volatile("createpolicy.fractional.L2::evict_last.b64 %0, 1.0;"  : "=l"(polLast));
    asm volatile("createpolicy.fractional.L2::evict_first.b64 %0, 1.0;" : "=l"(polFirst));

    if (tid == 0) {
#pragma unroll
        for (int s = 0; s < NB; s++) {
            asm volatile("mbarrier.init.shared.b64 [%0], 1;" :: "r"(MB_FULL(s))  : "memory");
            asm volatile("mbarrier.init.shared.b64 [%0], %1;" :: "r"(MB_CONS(s)), "r"(CWARPS) : "memory");
            asm volatile("mbarrier.init.shared.b64 [%0], %1;" :: "r"(MB_OFULL(s)), "r"(CWARPS) : "memory");
            asm volatile("mbarrier.init.shared.b64 [%0], 1;" :: "r"(MB_OFREE(s)) : "memory");
        }
    }
    __syncthreads();

    // ======================= LOADER WARP (wid 8) =======================
    if (wid == CWARPS) {
        if (lane == 0) {
            const float* srcP = pred + (gstart - (size_t)pad);
            const float* srcG = gt   + (gstart - (size_t)pad);
            for (int k = 0; k < 2 * NC; k++) {
                int c = (k < NC) ? k : (k - NC);
                int s = k % NB;
                if (k >= NB) mbar_wait(MB_CONS(s), (uint32_t)((k / NB - 1) & 1));
                int e0 = Eof(c, EF), e1 = Eof(c + 1, EF);
                uint32_t bytes = (uint32_t)(e1 - e0) * 4u;
                uint64_t pol = (k < NC) ? polLast : polFirst;
                asm volatile("mbarrier.arrive.expect_tx.shared.b64 _, [%0], %1;"
                             :: "r"(MB_FULL(s)), "r"(2u * bytes) : "memory");
                asm volatile("cp.async.bulk.shared::cluster.global.mbarrier::complete_tx::bytes.L2::cache_hint"
                             " [%0], [%1], %2, [%3], %4;"
                             :: "r"(smem_addr(predR + s * CHUNK)), "l"(srcP + e0), "r"(bytes),
                                "r"(MB_FULL(s)), "l"(pol) : "memory");
                asm volatile("cp.async.bulk.shared::cluster.global.mbarrier::complete_tx::bytes.L2::cache_hint"
                             " [%0], [%1], %2, [%3], %4;"
                             :: "r"(smem_addr(gtR + s * CHUNK)), "l"(srcG + e0), "r"(bytes),
                                "r"(MB_FULL(s)), "l"(pol) : "memory");
            }
        }
        return;
    }

    // ======================= STORER WARP (wid 9) =======================
    if (wid == CWARPS + 1) {
        if (lane == 0) {
            const int tailAligned = (pad + BF) & ~3;
            for (int cB = 0; cB < NC; cB++) {
                int o = cB % NB;
                mbar_wait(MB_OFULL(o), (uint32_t)((cB / NB) & 1));
                asm volatile("fence.proxy.async.shared::cta;" ::: "memory");
                int e0 = Eof(cB, EF), e1 = Eof(cB + 1, EF);
                int sl0 = (cB == 0 && pad) ? 4 : e0;
                int sl1 = (e1 < tailAligned) ? e1 : tailAligned;
                uint32_t sb = (uint32_t)(sl1 - sl0) * 4u;
                float* slotBase = outR + o * CHUNK;
                asm volatile("cp.async.bulk.global.shared::cta.bulk_group.L2::cache_hint [%0], [%1], %2, %3;"
                             :: "l"(out + gstart - (size_t)pad + sl0),
                                "r"(smem_addr(slotBase + (sl0 - e0))), "r"(sb), "l"(polFirst) : "memory");
                asm volatile("cp.async.bulk.commit_group;" ::: "memory");
                if (cB == 0 && pad) {                    // elements 0,1 at stream l=2,3
                    out[gstart]     = slotBase[2];
                    out[gstart + 1] = slotBase[3];
                }
                if (cB == NC - 1 && !pad) {              // tail elements 20668,20669
                    out[gstart + BF - 2] = slotBase[(BF - 2) - e0];
                    out[gstart + BF - 1] = slotBase[(BF - 1) - e0];
                }
                if (cB >= 2) {
                    asm volatile("cp.async.bulk.wait_group 2;" ::: "memory");
                    mbar_arrive(MB_OFREE((cB - 2) % NB));
                }
            }
            asm volatile("cp.async.bulk.wait_group 0;" ::: "memory");
        }
        return;
    }

    // ======================= CONSUMER WARPS (wid 0..7) =======================
    // ---- Pass A: streamed 16-stat reduction ----
    float acc[16];
#pragma unroll
    for (int i = 0; i < 16; i++) acc[i] = 0.f;

    for (int k = 0; k < NC; k++) {
        int s = k % NB;
        mbar_wait(MB_FULL(s), (uint32_t)((k / NB) & 1));
        int e0 = Eof(k, EF), e1 = Eof(k + 1, EF);
        const float* pc = predR + s * CHUNK - e0;
        const float* gc = gtR   + s * CHUNK - e0;
        int uS = (e0 - pad + 5) / 6;
        int uE = (e1 - pad) / 6; if (uE > NU) uE = NU;
        for (int u = uS + tid; u < uE; u += CTHREADS) {
            int l = pad + 6 * u;
            float2 pa = *(const float2*)(pc + l);
            float2 pb = *(const float2*)(pc + l + 2);
            float2 pcc = *(const float2*)(pc + l + 4);
            float2 ga = *(const float2*)(gc + l);
            float2 gb = *(const float2*)(gc + l + 2);
            float2 gcc = *(const float2*)(gc + l + 4);
            accum_pt(acc, pa.x, pa.y, pb.x, ga.x, ga.y, gb.x);
            accum_pt(acc, pb.y, pcc.x, pcc.y, gb.y, gcc.x, gcc.y);
        }
        __syncwarp();
        if (lane == 0) mbar_arrive(MB_CONS(s));
    }

    // block reduction among the 8 consumer warps (named barrier 1, 256 threads)
#pragma unroll
    for (int i = 0; i < 16; i++) {
        float v = acc[i];
        v += __shfl_down_sync(0xffffffffu, v, 16);
        v += __shfl_down_sync(0xffffffffu, v, 8);
        v += __shfl_down_sync(0xffffffffu, v, 4);
        v += __shfl_down_sync(0xffffffffu, v, 2);
        v += __shfl_down_sync(0xffffffffu, v, 1);
        acc[i] = v;
    }
    if (lane == 0) {
#pragma unroll
        for (int i = 0; i < 16; i++) redS[wid * 16 + i] = acc[i];
    }
    asm volatile("bar.sync 1, %0;" :: "n"(CTHREADS) : "memory");
    if (tid < 16) {
        float s = redS[tid];
#pragma unroll
        for (int w = 1; w < CWARPS; w++) s += redS[w * 16 + tid];
        statS[tid] = s;
    }
    asm volatile("bar.sync 1, %0;" :: "n"(CTHREADS) : "memory");

    // ---- thread 0: 3x3 Procrustes solve (overflow-safe fp32 Jacobi) ----
    if (tid == 0) {
        const float fN = (float)NPTS;
        const float invN = 1.0f / fN;
        float mu1[3], mu2[3];
#pragma unroll
        for (int i = 0; i < 3; i++) { mu1[i] = statS[i] * invN; mu2[i] = statS[3 + i] * invN; }

        float K[3][3];
#pragma unroll
        for (int i = 0; i < 3; i++)
#pragma unroll
            for (int j = 0; j < 3; j++)
                K[i][j] = statS[7 + 3 * i + j] - fN * mu1[i] * mu2[j] + 1e-8f;

        float var1 = statS[6] - fN * (mu1[0]*mu1[0] + mu1[1]*mu1[1] + mu1[2]*mu1[2]);

        float A[3][3];
#pragma unroll
        for (int i = 0; i < 3; i++)
#pragma unroll
            for (int j = 0; j < 3; j++)
                A[i][j] = K[0][i]*K[0][j] + K[1][i]*K[1][j] + K[2][i]*K[2][j];

        float V[3][3] = { {1.f,0.f,0.f}, {0.f,1.f,0.f}, {0.f,0.f,1.f} };

        for (int sweep = 0; sweep < 6; sweep++) {
#pragma unroll
            for (int pair = 0; pair < 3; pair++) {
                int p = (pair == 2) ? 1 : 0;
                int q = (pair == 0) ? 1 : 2;
                float apq = A[p][q];
                if (fabsf(apq) > 1e-18f) {
                    float tau = (A[q][q] - A[p][p]) / (2.f * apq);
                    float tt = copysignf(1.f, tau) / (fabsf(tau) + sqrtf(fmaf(tau, tau, 1.f)));
                    float c = rsqrtf(fmaf(tt, tt, 1.f));
                    float s = tt * c;
#pragma unroll
                    for (int kk = 0; kk < 3; kk++) {
                        float akp = A[kk][p], akq = A[kk][q];
                        A[kk][p] = c*akp - s*akq;
                        A[kk][q] = s*akp + c*akq;
                    }
#pragma unroll
                    for (int kk = 0; kk < 3; kk++) {
                        float apk = A[p][kk], aqk = A[q][kk];
                        A[p][kk] = c*apk - s*aqk;
                        A[q][kk] = s*apk + c*aqk;
                    }
#pragma unroll
                    for (int kk = 0; kk < 3; kk++) {
                        float vkp = V[kk][p], vkq = V[kk][q];
                        V[kk][p] = c*vkp - s*vkq;
                        V[kk][q] = s*vkp + c*vkq;
                    }
                }
            }
        }

        float dd[3] = { A[0][0], A[1][1], A[2][2] };
        int oo[3] = { 0, 1, 2 };
        if (dd[oo[0]] < dd[oo[1]]) { int t = oo[0]; oo[0] = oo[1]; oo[1] = t; }
        if (dd[oo[0]] < dd[oo[2]]) { int t = oo[0]; oo[0] = oo[2]; oo[2] = t; }
        if (dd[oo[1]] < dd[oo[2]]) { int t = oo[1]; oo[1] = oo[2]; oo[2] = t; }

        float v0[3], v1[3], v2[3];
#pragma unroll
        for (int i = 0; i < 3; i++) { v0[i] = V[i][oo[0]]; v1[i] = V[i][oo[1]]; v2[i] = V[i][oo[2]]; }
        float det =
            v0[0]*(v1[1]*v2[2] - v1[2]*v2[1]) -
            v0[1]*(v1[0]*v2[2] - v1[2]*v2[0]) +
            v0[2]*(v1[0]*v2[1] - v1[1]*v2[0]);
        if (det < 0.f) { v2[0] = -v2[0]; v2[1] = -v2[1]; v2[2] = -v2[2]; }

        float Kv0[3], Kv1[3];
#pragma unroll
        for (int i = 0; i < 3; i++) {
            Kv0[i] = K[i][0]*v0[0] + K[i][1]*v0[1] + K[i][2]*v0[2];
            Kv1[i] = K[i][0]*v1[0] + K[i][1]*v1[1] + K[i][2]*v1[2];
        }
        float r0 = rsqrtf(Kv0[0]*Kv0[0] + Kv0[1]*Kv0[1] + Kv0[2]*Kv0[2] + 1e-30f);
        float u0[3] = { Kv0[0]*r0, Kv0[1]*r0, Kv0[2]*r0 };
        float d01 = u0[0]*Kv1[0] + u0[1]*Kv1[1] + u0[2]*Kv1[2];
        float u1r[3] = { Kv1[0]-d01*u0[0], Kv1[1]-d01*u0[1], Kv1[2]-d01*u0[2] };
        float r1 = rsqrtf(u1r[0]*u1r[0] + u1r[1]*u1r[1] + u1r[2]*u1r[2] + 1e-30f);
        float u1[3] = { u1r[0]*r1, u1r[1]*r1, u1r[2]*r1 };
        float w[3] = { u0[1]*u1[2] - u0[2]*u1[1],
                       u0[2]*u1[0] - u0[0]*u1[2],
                       u0[0]*u1[1] - u0[1]*u1[0] };

        float R[3][3];
#pragma unroll
        for (int i = 0; i < 3; i++)
#pragma unroll
            for (int j = 0; j < 3; j++)
                R[i][j] = v0[i]*u0[j] + v1[i]*u1[j] + v2[i]*w[j];

        float tr = 0.f;
#pragma unroll
        for (int i = 0; i < 3; i++)
#pragma unroll
            for (int j = 0; j < 3; j++)
                tr += R[i][j] * K[j][i];
        float scale = tr / var1;

#pragma unroll
        for (int i = 0; i < 3; i++)
#pragma unroll
            for (int j = 0; j < 3; j++)
                R[i][j] *= scale;
#pragma unroll
        for (int i = 0; i < 3; i++)
            prm[9 + i] = mu2[i] - (R[i][0]*mu1[0] + R[i][1]*mu1[1] + R[i][2]*mu1[2]);
#pragma unroll
        for (int i = 0; i < 3; i++)
#pragma unroll
            for (int j = 0; j < 3; j++)
                prm[3 * i + j] = R[i][j];
    }
    asm volatile("bar.sync 1, %0;" :: "n"(CTHREADS) : "memory");

    float Rs[9], tv[3];
#pragma unroll
    for (int i = 0; i < 9; i++) Rs[i] = prm[i];
    tv[0] = prm[9]; tv[1] = prm[10]; tv[2] = prm[11];

    // ---- Pass B: streamed apply into out ring ----
    for (int k = NC; k < 2 * NC; k++) {
        int cB = k - NC;
        int s = k % NB;
        int o = cB % NB;
        if (cB >= NB) mbar_wait(MB_OFREE(o), (uint32_t)((cB / NB - 1) & 1));
        mbar_wait(MB_FULL(s), (uint32_t)((k / NB) & 1));
        int e0 = Eof(cB, EF), e1 = Eof(cB + 1, EF);
        const float* pc = predR + s * CHUNK - e0;
        const float* gc = gtR   + s * CHUNK - e0;
        float* oc = outR + o * CHUNK - e0;
        int uS = (e0 - pad + 5) / 6;
        int uE = (e1 - pad) / 6; if (uE > NU) uE = NU;
        for (int u = uS + tid; u < uE; u += CTHREADS) {
            int l = pad + 6 * u;
            float2 pa = *(const float2*)(pc + l);
            float2 pb = *(const float2*)(pc + l + 2);
            float2 pcc = *(const float2*)(pc + l + 4);
            float2 ga = *(const float2*)(gc + l);
            float2 gb = *(const float2*)(gc + l + 2);
            float2 gcc = *(const float2*)(gc + l + 4);

            float p0x = pa.x, p0y = pa.y, p0z = pb.x;
            float p1x = pb.y, p1y = pcc.x, p1z = pcc.y;

            float o0x = fabsf(fmaf(Rs[0], p0x, fmaf(Rs[1], p0y, fmaf(Rs[2], p0z, tv[0]))) - ga.x);
            float o0y = fabsf(fmaf(Rs[3], p0x, fmaf(Rs[4], p0y, fmaf(Rs[5], p0z, tv[1]))) - ga.y);
            float o0z = fabsf(fmaf(Rs[6], p0x, fmaf(Rs[7], p0y, fmaf(Rs[8], p0z, tv[2]))) - gb.x);
            float o1x = fabsf(fmaf(Rs[0], p1x, fmaf(Rs[1], p1y, fmaf(Rs[2], p1z, tv[0]))) - gb.y);
            float o1y = fabsf(fmaf(Rs[3], p1x, fmaf(Rs[4], p1y, fmaf(Rs[5], p1z, tv[1]))) - gcc.x);
            float o1z = fabsf(fmaf(Rs[6], p1x, fmaf(Rs[7], p1y, fmaf(Rs[8], p1z, tv[2]))) - gcc.y);

            *(float2*)(oc + l)     = make_float2(o0x, o0y);
            *(float2*)(oc + l + 2) = make_float2(o0z, o1x);
            *(float2*)(oc + l + 4) = make_float2(o1y, o1z);
        }
        __syncwarp();
        if (lane == 0) {
            mbar_arrive(MB_CONS(s));
            mbar_arrive(MB_OFULL(o));
        }
    }
}

extern "C" void kernel_launch(void* const* d_in, const int* in_sizes, int n_in,
                              void* d_out, int out_size) {
    const float* pred = (const float*)d_in[0];
    const float* gt   = (const float*)d_in[1];
    float* out = (float*)d_out;
    int B = in_sizes[0] / BF;   // 1024

    cudaFuncSetAttribute(procrustes_l1_kernel,
                         cudaFuncAttributeMaxDynamicSharedMemorySize, SMEM_BYTES);
    procrustes_l1_kernel<<<B, THREADS, SMEM_BYTES>>>(pred, gt, out);
}